// round 10
// baseline (speedup 1.0000x reference)
#include <cuda_runtime.h>

// ---------------------------------------------------------------------------
// SRR CG: out = relu(CG(AtA, b=At(slices), x0=volume, 10 iters))
// R10 on top of R9's fused AtA:
//  - paired-row layout (thread handles pixels (h, h+64)): grid=512 -> exactly
//    one wave at 4 blocks/SM, and in/out-of-range work is balanced per pair.
//  - no k_fin launches: consumers redundantly finalize partial-sum arrays
//    per block (deterministic tree, L2-hot reads).
//  - b eliminated: At(slices) scatters straight into r (b was only r's init).
// Scratch only via __device__ globals referenced INSIDE kernels.
// ---------------------------------------------------------------------------

#define NVOX (128*128*128)
#define NPIX (16*128*128)
#define TPB 256
#define NBLK 1024                 // blocks for 16MB elementwise passes
#define PAIR_BLOCKS 512           // (NPIX/2)/TPB — pixel-pair kernels

__device__ float g_x[NVOX];
__device__ float g_r[NVOX];
__device__ float g_p[NVOX];
__device__ float g_Ap[NVOX];
__device__ double g_part_pAp[PAIR_BLOCKS];
__device__ double g_part_rr[2][NBLK];

// --------------------------- per-pixel frame -------------------------------

struct Frame {
    float R[9];
    float cx, cy, cz;
};

__device__ __forceinline__ Frame make_frame(int idx, const float* __restrict__ theta) {
    int w = idx & 127;
    int h = (idx >> 7) & 127;
    int n = idx >> 14;
    const float* T = theta + n * 12;
    Frame f;
    f.R[0] = T[0];  f.R[1] = T[1];  f.R[2] = T[2];
    f.R[3] = T[4];  f.R[4] = T[5];  f.R[5] = T[6];
    f.R[6] = T[8];  f.R[7] = T[9];  f.R[8] = T[10];
    float u = ((float)w - 63.5f) * 1.5f;
    float v = ((float)h - 63.5f) * 1.5f;
    f.cx = f.R[0]*u + f.R[1]*v + T[3]  + 63.5f;
    f.cy = f.R[3]*u + f.R[4]*v + T[7]  + 63.5f;
    f.cz = f.R[6]*u + f.R[7]*v + T[11] + 63.5f;
    return f;
}

// Center further than (sqrt(3) rotated PSF offset + 1 trilinear corner)
// outside [0,127] in any axis -> whole footprint out of bounds -> zero.
__device__ __forceinline__ bool in_range(const Frame& f) {
    return f.cx > -2.75f && f.cx < 129.75f &&
           f.cy > -2.75f && f.cy < 129.75f &&
           f.cz > -2.75f && f.cz < 129.75f;
}

// --------------------------- reductions ------------------------------------

__device__ __forceinline__ void block_reduce_store(double s, double* dst) {
    __shared__ double sm[TPB];
    sm[threadIdx.x] = s;
    __syncthreads();
    for (int off = TPB / 2; off > 0; off >>= 1) {
        if (threadIdx.x < off) sm[threadIdx.x] += sm[threadIdx.x + off];
        __syncthreads();
    }
    if (threadIdx.x == 0) dst[blockIdx.x] = sm[0];
}

// Reduce two values; every thread gets both sums (deterministic tree).
__device__ __forceinline__ void block_reduce2_all(double a, double b,
                                                  double& outa, double& outb) {
    __shared__ double smA[TPB], smB[TPB];
    smA[threadIdx.x] = a;
    smB[threadIdx.x] = b;
    __syncthreads();
    for (int off = TPB / 2; off > 0; off >>= 1) {
        if (threadIdx.x < off) {
            smA[threadIdx.x] += smA[threadIdx.x + off];
            smB[threadIdx.x] += smB[threadIdx.x + off];
        }
        __syncthreads();
    }
    outa = smA[0];
    outb = smB[0];
    __syncthreads();
}

// --------------------------- gather / scatter cores ------------------------

__device__ __forceinline__ float gather27(const Frame& f,
                                          const float* __restrict__ vol,
                                          const float* __restrict__ psf) {
    float acc = 0.f;
    int k = 0;
    #pragma unroll
    for (int a = -1; a <= 1; a++) {
        float oz = (float)a;
        #pragma unroll
        for (int b = -1; b <= 1; b++) {
            float oy = (float)b;
            #pragma unroll
            for (int c = -1; c <= 1; c++, k++) {
                float ox = (float)c;
                float px = f.cx + f.R[0]*ox + f.R[1]*oy + f.R[2]*oz;
                float py = f.cy + f.R[3]*ox + f.R[4]*oy + f.R[5]*oz;
                float pz = f.cz + f.R[6]*ox + f.R[7]*oy + f.R[8]*oz;
                float pk = __ldg(&psf[k]);
                float xf = floorf(px), yf = floorf(py), zf = floorf(pz);
                int x0 = (int)xf, y0 = (int)yf, z0 = (int)zf;
                float fx = px - xf, fy = py - yf, fz = pz - zf;
                float wx0 = 1.f - fx, wy0 = 1.f - fy, wz0 = 1.f - fz;
                float s = 0.f;
                #pragma unroll
                for (int dz = 0; dz < 2; dz++) {
                    float wz = dz ? fz : wz0;
                    int zi = z0 + dz;
                    #pragma unroll
                    for (int dy = 0; dy < 2; dy++) {
                        float wy = dy ? fy : wy0;
                        int yi = y0 + dy;
                        #pragma unroll
                        for (int dx = 0; dx < 2; dx++) {
                            float wx = dx ? fx : wx0;
                            int xi = x0 + dx;
                            if ((unsigned)xi < 128u && (unsigned)yi < 128u && (unsigned)zi < 128u)
                                s += wx * wy * wz * __ldg(&vol[(zi * 128 + yi) * 128 + xi]);
                        }
                    }
                }
                acc += pk * s;
            }
        }
    }
    return acc;
}

__device__ __forceinline__ void scatter27(const Frame& f, float* __restrict__ vol,
                                          const float* __restrict__ psf, float val) {
    int k = 0;
    #pragma unroll
    for (int a = -1; a <= 1; a++) {
        float oz = (float)a;
        #pragma unroll
        for (int b = -1; b <= 1; b++) {
            float oy = (float)b;
            #pragma unroll
            for (int c = -1; c <= 1; c++, k++) {
                float ox = (float)c;
                float px = f.cx + f.R[0]*ox + f.R[1]*oy + f.R[2]*oz;
                float py = f.cy + f.R[3]*ox + f.R[4]*oy + f.R[5]*oz;
                float pz = f.cz + f.R[6]*ox + f.R[7]*oy + f.R[8]*oz;
                float base = val * __ldg(&psf[k]);
                float xf = floorf(px), yf = floorf(py), zf = floorf(pz);
                int x0 = (int)xf, y0 = (int)yf, z0 = (int)zf;
                float fx = px - xf, fy = py - yf, fz = pz - zf;
                float wx0 = 1.f - fx, wy0 = 1.f - fy, wz0 = 1.f - fz;
                #pragma unroll
                for (int dz = 0; dz < 2; dz++) {
                    int zi = z0 + dz;
                    if ((unsigned)zi >= 128u) continue;
                    float bz = base * (dz ? fz : wz0);
                    #pragma unroll
                    for (int dy = 0; dy < 2; dy++) {
                        int yi = y0 + dy;
                        if ((unsigned)yi >= 128u) continue;
                        float byz = bz * (dy ? fy : wy0);
                        float* row = vol + (zi * 128 + yi) * 128;
                        if ((unsigned)x0 < 128u)       atomicAdd(row + x0,     byz * wx0);
                        if ((unsigned)(x0 + 1) < 128u) atomicAdd(row + x0 + 1, byz * fx);
                    }
                }
            }
        }
    }
}

// Pair mapping: linear li in [0, NPIX/2) -> pixel (n, h<64, w); partner is
// (n, h+64, w) = idx + 8192. Pairs mix in-range and out-of-range rows.
__device__ __forceinline__ int pair_base(int li) {
    int n = li >> 13;
    int rem = li & 8191;
    return n * 16384 + rem;
}

// --------------------------- fused AtA kernel ------------------------------
// Per pixel: a = <w, src>;  dst += sign * a * w;  optional pAp partials (a^2).
// src_sel: 0 -> g_x, 1 -> g_p.   dst_sel: 1 -> g_r, 2 -> g_Ap.

__global__ void k_AtA(const float* __restrict__ theta, const float* __restrict__ psf,
                      int src_sel, int dst_sel, float sign, int do_dot) {
    const float* __restrict__ src = src_sel == 0 ? g_x : g_p;
    float* __restrict__ dst = dst_sel == 1 ? g_r : g_Ap;
    int li = blockIdx.x * TPB + threadIdx.x;
    int base = pair_base(li);
    double dot = 0.0;
    #pragma unroll 1
    for (int pp = 0; pp < 2; pp++) {
        int idx = base + pp * 8192;
        Frame f = make_frame(idx, theta);
        float acc = 0.f;
        if (in_range(f)) {
            acc = gather27(f, src, psf);
            float val = sign * acc;
            if (val != 0.f)
                scatter27(f, dst, psf, val);
        }
        dot += (double)acc * (double)acc;
    }
    if (do_dot)
        block_reduce_store(dot, g_part_pAp);
}

// --------------------------- At (slices -> r) ------------------------------

__global__ void k_At_slices(const float* __restrict__ theta, const float* __restrict__ psf,
                            const float* __restrict__ slices) {
    int li = blockIdx.x * TPB + threadIdx.x;
    int base = pair_base(li);
    #pragma unroll 1
    for (int pp = 0; pp < 2; pp++) {
        int idx = base + pp * 8192;
        Frame f = make_frame(idx, theta);
        if (!in_range(f)) continue;
        float val = slices[idx];
        if (val != 0.f)
            scatter27(f, g_r, psf, val);
    }
}

// --------------------------- elementwise / CG vector kernels ---------------

// r = 0, Ap = 0, x = volume (single pass)
__global__ void k_init(const float* __restrict__ volume) {
    float4* r4  = (float4*)g_r;
    float4* a4  = (float4*)g_Ap;
    float4* x4  = (float4*)g_x;
    const float4* v4 = (const float4*)volume;
    float4 z = make_float4(0.f, 0.f, 0.f, 0.f);
    for (int i = blockIdx.x * TPB + threadIdx.x; i < NVOX/4; i += TPB * NBLK) {
        r4[i] = z;
        a4[i] = z;
        x4[i] = v4[i];
    }
}

__global__ void k_relu(float* __restrict__ out) {
    float4* o4 = (float4*)out;
    const float4* x4 = (const float4*)g_x;
    for (int i = blockIdx.x * TPB + threadIdx.x; i < NVOX/4; i += TPB * NBLK) {
        float4 v = x4[i];
        o4[i] = make_float4(fmaxf(v.x, 0.f), fmaxf(v.y, 0.f),
                            fmaxf(v.z, 0.f), fmaxf(v.w, 0.f));
    }
}

// p = r; rr partials -> g_part_rr[0]
__global__ void k_initp() {
    double s = 0.0;
    const float4* r4 = (const float4*)g_r;
    float4* p4 = (float4*)g_p;
    for (int i = blockIdx.x * TPB + threadIdx.x; i < NVOX/4; i += TPB * NBLK) {
        float4 rv = r4[i];
        p4[i] = rv;
        s += (double)rv.x*rv.x + (double)rv.y*rv.y + (double)rv.z*rv.z + (double)rv.w*rv.w;
    }
    block_reduce_store(s, g_part_rr[0]);
}

// Finalize alpha = rr_old/pAp per block (redundant, deterministic), then
// x += alpha p; r -= alpha Ap; rr_new partials -> g_part_rr[nxt].
__global__ void k_update_xr(int cur) {
    int t = threadIdx.x;
    double rr_l = g_part_rr[cur][t] + g_part_rr[cur][t + 256]
                + g_part_rr[cur][t + 512] + g_part_rr[cur][t + 768];
    double pp_l = g_part_pAp[t] + g_part_pAp[t + 256];
    double rr_old, pAp;
    block_reduce2_all(rr_l, pp_l, rr_old, pAp);
    float alpha = (float)(rr_old / pAp);

    double s = 0.0;
    float4* x4 = (float4*)g_x;
    float4* r4 = (float4*)g_r;
    const float4* p4 = (const float4*)g_p;
    const float4* a4 = (const float4*)g_Ap;
    for (int i = blockIdx.x * TPB + t; i < NVOX/4; i += TPB * NBLK) {
        float4 xv = x4[i], rv = r4[i], pv = p4[i], av = a4[i];
        xv.x += alpha * pv.x; xv.y += alpha * pv.y;
        xv.z += alpha * pv.z; xv.w += alpha * pv.w;
        rv.x -= alpha * av.x; rv.y -= alpha * av.y;
        rv.z -= alpha * av.z; rv.w -= alpha * av.w;
        x4[i] = xv; r4[i] = rv;
        s += (double)rv.x*rv.x + (double)rv.y*rv.y + (double)rv.z*rv.z + (double)rv.w*rv.w;
    }
    block_reduce_store(s, g_part_rr[cur ^ 1]);
}

// Finalize beta = rr_new/rr_old per block, then p = r + beta p; Ap = 0.
__global__ void k_update_p(int cur) {
    int t = threadIdx.x;
    int nxt = cur ^ 1;
    double rrn_l = g_part_rr[nxt][t] + g_part_rr[nxt][t + 256]
                 + g_part_rr[nxt][t + 512] + g_part_rr[nxt][t + 768];
    double rro_l = g_part_rr[cur][t] + g_part_rr[cur][t + 256]
                 + g_part_rr[cur][t + 512] + g_part_rr[cur][t + 768];
    double rr_new, rr_old;
    block_reduce2_all(rrn_l, rro_l, rr_new, rr_old);
    float beta = (float)(rr_new / rr_old);

    float4* p4 = (float4*)g_p;
    float4* a4 = (float4*)g_Ap;
    const float4* r4 = (const float4*)g_r;
    float4 z = make_float4(0.f, 0.f, 0.f, 0.f);
    for (int i = blockIdx.x * TPB + t; i < NVOX/4; i += TPB * NBLK) {
        float4 rv = r4[i], pv = p4[i];
        pv.x = rv.x + beta * pv.x; pv.y = rv.y + beta * pv.y;
        pv.z = rv.z + beta * pv.z; pv.w = rv.w + beta * pv.w;
        p4[i] = pv;
        a4[i] = z;
    }
}

// --------------------------- driver ----------------------------------------

extern "C" void kernel_launch(void* const* d_in, const int* in_sizes, int n_in,
                              void* d_out, int out_size) {
    const float* theta  = (const float*)d_in[0];
    const float* slices = (const float*)d_in[1];
    const float* volume = (const float*)d_in[2];
    const float* psf    = (const float*)d_in[3];
    float* out = (float*)d_out;
    (void)in_sizes; (void)n_in; (void)out_size;

    // r = At(slices) - AtA(x);  x = volume;  p = r; rr partials
    k_init<<<NBLK, TPB>>>(volume);
    k_At_slices<<<PAIR_BLOCKS, TPB>>>(theta, psf, slices);
    k_AtA<<<PAIR_BLOCKS, TPB>>>(theta, psf, 0, 1, -1.f, 0);
    k_initp<<<NBLK, TPB>>>();

    int cur = 0;
    for (int it = 0; it < 10; it++) {
        // Ap = AtA(p); pAp partials fused
        k_AtA<<<PAIR_BLOCKS, TPB>>>(theta, psf, 1, 2, 1.f, 1);
        // x,r update (finalizes alpha in-block) + rr_new partials
        k_update_xr<<<NBLK, TPB>>>(cur);
        // p update (finalizes beta in-block) + zero Ap
        k_update_p<<<NBLK, TPB>>>(cur);
        cur ^= 1;
    }

    k_relu<<<NBLK, TPB>>>(out);
}